// round 1
// baseline (speedup 1.0000x reference)
#include <cuda_runtime.h>
#include <cuda_bf16.h>
#include <cstdint>

// Problem constants (fixed by setup_inputs)
#define TT  128   // dim_label_emb
#define C0_ 512   // num_class0
#define C1_ 1024  // num_class1
#define NTHREADS 256

// Per-t partial stats: [t][0]=sum(E^2), [t][1]=sum(rowsum^2), [t][2]=sum(colsum^2), [t][3]=S_t
__device__ float g_part[TT * 4];

__device__ __forceinline__ float warp_red(float v) {
    v += __shfl_xor_sync(0xffffffffu, v, 16);
    v += __shfl_xor_sync(0xffffffffu, v, 8);
    v += __shfl_xor_sync(0xffffffffu, v, 4);
    v += __shfl_xor_sync(0xffffffffu, v, 2);
    v += __shfl_xor_sync(0xffffffffu, v, 1);
    return v;
}

// One block per t (128 blocks, 256 threads). Thread owns 4 contiguous columns
// (one float4) and streams all 512 rows i (row r = i*128 + t).
__global__ void __launch_bounds__(NTHREADS, 1)
lcl_pass1(const float* __restrict__ A) {
    const int t    = blockIdx.x;
    const int tid  = threadIdx.x;
    const int lane = tid & 31;
    const int warp = tid >> 5;

    // float4 view: row has C1/4 = 256 float4s; i-stride = T * 256 = 32768 float4s
    const float4* __restrict__ base =
        reinterpret_cast<const float4*>(A) + (size_t)t * (C1_ / 4) + tid;
    const size_t istride = (size_t)TT * (C1_ / 4);

    float4 cs = make_float4(0.f, 0.f, 0.f, 0.f);  // per-thread colsums (final, since block sees all i)
    float  sumsq = 0.f;                            // Σ E² partial
    float  rs2   = 0.f;                            // Σ rowsum² partial (only tid<32 accumulate)

    __shared__ float rowpart[32][9];  // [row-in-chunk][warp], padded (9 coprime w/ 32 banks)

    for (int i0 = 0; i0 < C0_; i0 += 32) {
        #pragma unroll 8
        for (int i = 0; i < 32; ++i) {
            float4 v = __ldg(base + (size_t)(i0 + i) * istride);
            sumsq = fmaf(v.x, v.x, sumsq);
            sumsq = fmaf(v.y, v.y, sumsq);
            sumsq = fmaf(v.z, v.z, sumsq);
            sumsq = fmaf(v.w, v.w, sumsq);
            cs.x += v.x; cs.y += v.y; cs.z += v.z; cs.w += v.w;
            float s = (v.x + v.y) + (v.z + v.w);   // this thread's 4-col row partial
            s += __shfl_xor_sync(0xffffffffu, s, 16);
            s += __shfl_xor_sync(0xffffffffu, s, 8);
            s += __shfl_xor_sync(0xffffffffu, s, 4);
            s += __shfl_xor_sync(0xffffffffu, s, 2);
            s += __shfl_xor_sync(0xffffffffu, s, 1);
            if (lane == 0) rowpart[i][warp] = s;   // warp covers 128 columns
        }
        __syncthreads();
        if (tid < 32) {  // thread j finishes row (i0+j): sum the 8 warp partials
            float r = 0.f;
            #pragma unroll
            for (int w = 0; w < 8; ++w) r += rowpart[tid][w];
            rs2 = fmaf(r, r, rs2);
        }
        __syncthreads();
    }

    // Per-thread colsum stats (colsums are complete here)
    float csq  = cs.x * cs.x + cs.y * cs.y + cs.z * cs.z + cs.w * cs.w;
    float ctot = (cs.x + cs.y) + (cs.z + cs.w);

    // Block reduction of the 4 scalars
    __shared__ float red[4][8];
    sumsq = warp_red(sumsq);
    rs2   = warp_red(rs2);
    csq   = warp_red(csq);
    ctot  = warp_red(ctot);
    if (lane == 0) {
        red[0][warp] = sumsq;
        red[1][warp] = rs2;
        red[2][warp] = csq;
        red[3][warp] = ctot;
    }
    __syncthreads();
    if (tid < 4) {
        float acc = 0.f;
        #pragma unroll
        for (int w = 0; w < 8; ++w) acc += red[tid][w];
        g_part[t * 4 + tid] = acc;
    }
}

// Single block, 128 threads: combine per-t partials (double precision) and emit loss.
__global__ void lcl_final(float* __restrict__ out) {
    const int tid = threadIdx.x;  // 0..127 == t
    __shared__ double sh[4][TT];
    double st = (double)g_part[tid * 4 + 3];
    sh[0][tid] = (double)g_part[tid * 4 + 0];
    sh[1][tid] = (double)g_part[tid * 4 + 1];
    sh[2][tid] = (double)g_part[tid * 4 + 2];
    sh[3][tid] = st * st;
    __syncthreads();
    if (tid == 0) {
        double S2 = 0.0, R = 0.0, Csq = 0.0, SST2 = 0.0;
        for (int i = 0; i < TT; ++i) {
            S2   += sh[0][i];
            R    += sh[1][i];
            Csq  += sh[2][i];
            SST2 += sh[3][i];
        }
        const double c0 = (double)C0_, c1 = (double)C1_;
        double intra  = S2 - R / c1;
        double inter  = R / c1 - SST2 / (c0 * c1);
        double dintra = S2 - Csq / c0;
        double dinter = Csq / c0 - SST2 / (c0 * c1);
        double loss = 0.5 * (intra / inter + dintra / dinter) / (c0 * c1);
        out[0] = (float)loss;
    }
}

extern "C" void kernel_launch(void* const* d_in, const int* in_sizes, int n_in,
                              void* d_out, int out_size) {
    const float* A = (const float*)d_in[0];   // [C0*T, C1] float32
    float* out = (float*)d_out;               // scalar float32
    lcl_pass1<<<TT, NTHREADS>>>(A);
    lcl_final<<<1, TT>>>(out);
}

// round 4
// speedup vs baseline: 1.4887x; 1.4887x over previous
#include <cuda_runtime.h>
#include <cuda_bf16.h>
#include <cstdint>

// Problem constants (fixed by setup_inputs)
#define TT  128   // dim_label_emb
#define C0_ 512   // num_class0
#define C1_ 1024  // num_class1
#define NTHREADS 256
#define NWARPS   (NTHREADS / 32)
#define ISPLIT   4
#define ROWS_PER_BLK (C0_ / ISPLIT)   // 128

// Per-(split,t) column-sum partials: 4*128*1024 floats = 2 MB
__device__ float g_colpart[ISPLIT * TT * C1_];
// Per-(t,split) scalar partials: [t][sp][0]=sumsq, [1]=rowsum^2 sum, [2]=slice sum
__device__ float g_stats[TT * ISPLIT * 3];
// Per-t combined stats: [t][0]=sumsq, [1]=rs2, [2]=csq, [3]=st
__device__ float g_final[TT * 4];

__device__ __forceinline__ float warp_red(float v) {
    v += __shfl_xor_sync(0xffffffffu, v, 16);
    v += __shfl_xor_sync(0xffffffffu, v, 8);
    v += __shfl_xor_sync(0xffffffffu, v, 4);
    v += __shfl_xor_sync(0xffffffffu, v, 2);
    v += __shfl_xor_sync(0xffffffffu, v, 1);
    return v;
}

// 512 blocks: blockIdx = t + 128*split. Each block: 128 rows (i = sp*128+r),
// full 1024 columns. Warp-per-row: lane loads 8 float4 (cols lane*16b strided),
// so the whole row reduce costs ONE 5-shfl tree per 256 float4s.
__global__ void __launch_bounds__(NTHREADS)
lcl_pass1(const float* __restrict__ A) {
    const int t    = blockIdx.x & (TT - 1);
    const int sp   = blockIdx.x >> 7;
    const int lane = threadIdx.x & 31;
    const int warp = threadIdx.x >> 5;

    float4 cs[8];
    #pragma unroll
    for (int k = 0; k < 8; ++k) cs[k] = make_float4(0.f, 0.f, 0.f, 0.f);
    float sumsq = 0.f, rs2 = 0.f, st = 0.f;

    for (int r = warp; r < ROWS_PER_BLK; r += NWARPS) {
        const int i = sp * ROWS_PER_BLK + r;               // global class index
        const float4* __restrict__ rowp =
            reinterpret_cast<const float4*>(A) + ((size_t)i * TT + t) * (C1_ / 4);

        float4 v[8];
        #pragma unroll
        for (int k = 0; k < 8; ++k) v[k] = __ldg(rowp + k * 32 + lane);

        float rp = 0.f;
        #pragma unroll
        for (int k = 0; k < 8; ++k) {
            sumsq = fmaf(v[k].x, v[k].x, sumsq);
            sumsq = fmaf(v[k].y, v[k].y, sumsq);
            sumsq = fmaf(v[k].z, v[k].z, sumsq);
            sumsq = fmaf(v[k].w, v[k].w, sumsq);
            cs[k].x += v[k].x; cs[k].y += v[k].y;
            cs[k].z += v[k].z; cs[k].w += v[k].w;
            rp += (v[k].x + v[k].y) + (v[k].z + v[k].w);
        }
        rp = warp_red(rp);            // all lanes hold full rowsum
        rs2 = fmaf(rp, rp, rs2);      // identical across lanes; lane 0's used
        st += rp;
    }

    // ---- combine colsums across warps via smem (once per block) ----
    __shared__ float4 s_cs[NWARPS][C1_ / 4];   // 8 * 4KB = 32KB
    #pragma unroll
    for (int k = 0; k < 8; ++k) s_cs[warp][k * 32 + lane] = cs[k];

    // ---- reduce scalars ----
    __shared__ float s_red[3][NWARPS];
    sumsq = warp_red(sumsq);
    if (lane == 0) {
        s_red[0][warp] = sumsq;
        s_red[1][warp] = rs2;
        s_red[2][warp] = st;
    }
    __syncthreads();

    // each thread owns one float4 column group: sum 8 warp partials, store
    {
        float4 acc = s_cs[0][threadIdx.x];
        #pragma unroll
        for (int w = 1; w < NWARPS; ++w) {
            float4 p = s_cs[w][threadIdx.x];
            acc.x += p.x; acc.y += p.y; acc.z += p.z; acc.w += p.w;
        }
        reinterpret_cast<float4*>(g_colpart)[((size_t)sp * TT + t) * (C1_ / 4) + threadIdx.x] = acc;
    }

    if (threadIdx.x < 3) {
        float acc = 0.f;
        #pragma unroll
        for (int w = 0; w < NWARPS; ++w) acc += s_red[threadIdx.x][w];
        g_stats[(t * ISPLIT + sp) * 3 + threadIdx.x] = acc;
    }
}

// 128 blocks (one per t), 256 threads: combine the 4 split colsum partials,
// form per-t stats.
__global__ void __launch_bounds__(NTHREADS)
lcl_pass2() {
    const int t    = blockIdx.x;
    const int tid  = threadIdx.x;
    const int lane = tid & 31;
    const int warp = tid >> 5;

    float4 acc = make_float4(0.f, 0.f, 0.f, 0.f);
    #pragma unroll
    for (int sp = 0; sp < ISPLIT; ++sp) {
        float4 p = reinterpret_cast<const float4*>(g_colpart)[((size_t)sp * TT + t) * (C1_ / 4) + tid];
        acc.x += p.x; acc.y += p.y; acc.z += p.z; acc.w += p.w;
    }
    float csq = acc.x * acc.x + acc.y * acc.y + acc.z * acc.z + acc.w * acc.w;
    csq = warp_red(csq);

    __shared__ float s_csq[NWARPS];
    if (lane == 0) s_csq[warp] = csq;
    __syncthreads();

    if (tid == 0) {
        float c = 0.f;
        #pragma unroll
        for (int w = 0; w < NWARPS; ++w) c += s_csq[w];
        float sumsq = 0.f, rs2 = 0.f, st = 0.f;
        #pragma unroll
        for (int sp = 0; sp < ISPLIT; ++sp) {
            sumsq += g_stats[(t * ISPLIT + sp) * 3 + 0];
            rs2   += g_stats[(t * ISPLIT + sp) * 3 + 1];
            st    += g_stats[(t * ISPLIT + sp) * 3 + 2];
        }
        g_final[t * 4 + 0] = sumsq;
        g_final[t * 4 + 1] = rs2;
        g_final[t * 4 + 2] = c;
        g_final[t * 4 + 3] = st;
    }
}

// Single block: combine per-t stats in double, emit loss.
__global__ void lcl_final(float* __restrict__ out) {
    const int tid = threadIdx.x;  // 0..127 == t
    __shared__ double sh[4][TT];
    double st = (double)g_final[tid * 4 + 3];
    sh[0][tid] = (double)g_final[tid * 4 + 0];
    sh[1][tid] = (double)g_final[tid * 4 + 1];
    sh[2][tid] = (double)g_final[tid * 4 + 2];
    sh[3][tid] = st * st;
    __syncthreads();
    if (tid == 0) {
        double S2 = 0.0, R = 0.0, Csq = 0.0, SST2 = 0.0;
        for (int i = 0; i < TT; ++i) {
            S2   += sh[0][i];
            R    += sh[1][i];
            Csq  += sh[2][i];
            SST2 += sh[3][i];
        }
        const double c0 = (double)C0_, c1 = (double)C1_;
        double intra  = S2 - R / c1;
        double inter  = R / c1 - SST2 / (c0 * c1);
        double dintra = S2 - Csq / c0;
        double dinter = Csq / c0 - SST2 / (c0 * c1);
        double loss = 0.5 * (intra / inter + dintra / dinter) / (c0 * c1);
        out[0] = (float)loss;
    }
}

extern "C" void kernel_launch(void* const* d_in, const int* in_sizes, int n_in,
                              void* d_out, int out_size) {
    const float* A = (const float*)d_in[0];   // [C0*T, C1] float32
    float* out = (float*)d_out;               // scalar float32
    lcl_pass1<<<TT * ISPLIT, NTHREADS>>>(A);
    lcl_pass2<<<TT, NTHREADS>>>();
    lcl_final<<<1, TT>>>(out);
}